// round 14
// baseline (speedup 1.0000x reference)
#include <cuda_runtime.h>
#include <cuda_fp16.h>
#include <cstdint>

// Problem constants
#define Bb   2048
#define Nn   128
#define Cc   128
#define Hh   4
#define NW   64
#define M_TOT (Bb * Nn)
#define SCALE 0.1767766952966369f  // 1/sqrt(32)

// ---------------------------------------------------------------------------
// Helpers (baseline ISA: ldmatrix + mma.sync fp16 + cp.async)
// ---------------------------------------------------------------------------
__device__ __forceinline__ uint32_t smem_u32(const void* p) {
    uint32_t a;
    asm("{ .reg .u64 t; cvta.to.shared.u64 t, %1; cvt.u32.u64 %0, t; }"
        : "=r"(a) : "l"(p));
    return a;
}
__device__ __forceinline__ uint32_t pack_h2(float a, float b) {
    __half2 h = __floats2half2_rn(a, b);
    return *reinterpret_cast<uint32_t*>(&h);
}
__device__ __forceinline__ uint32_t pack_h2_lo(float a, float b) {
    float ah = __half2float(__float2half_rn(a));
    float bh = __half2float(__float2half_rn(b));
    return pack_h2(a - ah, b - bh);
}
__device__ __forceinline__ void ldsm4(uint32_t& r0, uint32_t& r1, uint32_t& r2,
                                      uint32_t& r3, uint32_t addr) {
    asm volatile("ldmatrix.sync.aligned.m8n8.x4.shared.b16 {%0,%1,%2,%3}, [%4];"
                 : "=r"(r0), "=r"(r1), "=r"(r2), "=r"(r3) : "r"(addr));
}
__device__ __forceinline__ void ldsm4t(uint32_t& r0, uint32_t& r1, uint32_t& r2,
                                       uint32_t& r3, uint32_t addr) {
    asm volatile("ldmatrix.sync.aligned.m8n8.x4.trans.shared.b16 {%0,%1,%2,%3}, [%4];"
                 : "=r"(r0), "=r"(r1), "=r"(r2), "=r"(r3) : "r"(addr));
}
__device__ __forceinline__ void mma_f16(float* c, const uint32_t* a,
                                        const uint32_t* b) {
    asm volatile(
        "mma.sync.aligned.m16n8k16.row.col.f32.f16.f16.f32 "
        "{%0,%1,%2,%3}, {%4,%5,%6,%7}, {%8,%9}, {%0,%1,%2,%3};"
        : "+f"(c[0]), "+f"(c[1]), "+f"(c[2]), "+f"(c[3])
        : "r"(a[0]), "r"(a[1]), "r"(a[2]), "r"(a[3]), "r"(b[0]), "r"(b[1]));
}
__device__ __forceinline__ void cp_async16(uint32_t saddr, const void* gaddr) {
    asm volatile("cp.async.cg.shared.global [%0], [%1], 16;"
                 :: "r"(saddr), "l"(gaddr));
}
#define CP_COMMIT() asm volatile("cp.async.commit_group;" ::: "memory")
#define CP_WAIT0()  asm volatile("cp.async.wait_group 0;" ::: "memory")

// ---------------------------------------------------------------------------
// Scratch
// ---------------------------------------------------------------------------
__device__ __half g_w16[3 * Cc * Cc];
__device__ __half g_pw16[Cc * Cc];
__device__ __half g_mask16[NW * Nn * Nn];

// ---------------------------------------------------------------------------
// Prepass: weights + mask -> fp16
// ---------------------------------------------------------------------------
#define MASK2  (NW * Nn * Nn / 2)
#define QW2    (3 * Cc * Cc / 2)
#define PW2    (Cc * Cc / 2)
#define PREP_TOT (MASK2 + QW2 + PW2)

__global__ void prep16(const float* __restrict__ mask,
                       const float* __restrict__ qkv_w,
                       const float* __restrict__ proj_w) {
    int idx = blockIdx.x * blockDim.x + threadIdx.x;
    if (idx >= PREP_TOT) return;
    if (idx < MASK2) {
        float2 v = reinterpret_cast<const float2*>(mask)[idx];
        reinterpret_cast<uint32_t*>(g_mask16)[idx] = pack_h2(v.x, v.y);
    } else if (idx < MASK2 + QW2) {
        float2 v = reinterpret_cast<const float2*>(qkv_w)[idx - MASK2];
        reinterpret_cast<uint32_t*>(g_w16)[idx - MASK2] = pack_h2(v.x, v.y);
    } else {
        float2 v = reinterpret_cast<const float2*>(proj_w)[idx - MASK2 - QW2];
        reinterpret_cast<uint32_t*>(g_pw16)[idx - MASK2 - QW2] = pack_h2(v.x, v.y);
    }
}

// ---------------------------------------------------------------------------
// FULLY FUSED kernel — HYBRID warp allocation (512 threads / 16 warps):
//   Phase 1 (QKV) + Phase 3 (proj): warps 0-7 only, 32x64 warp tiles (the
//     proven R9/R12 GEMM config; warps 8-15 wait at the barrier).
//   Phase 2 (attention): ALL 16 warps — warp handles (head = pair*2 + w>>3,
//     q-rows (w&7)*16..+16); 2 pair-iterations. Mask from gmem (L1-hot),
//     tree softmax, register-repacked PV.
// smem: XA/PW 32K | B0/ATT 32K | Q 32K | KHI 32K | KLO 32K | VR/V 32K =192KB.
// ---------------------------------------------------------------------------
#define FSM_XA   0
#define FSM_B0   32768
#define FSM_Q    65536
#define FSM_KHI  98304
#define FSM_KLO  131072
#define FSM_VR   163840
#define FSM_TOTAL 196608

#define NT 512

__device__ __forceinline__ uint32_t prow_addr(int r, int u) {
    return (uint32_t)((r >> 1) * 128 + 16 * ((((r & 1) * 4) + u) ^ ((r >> 1) & 7)));
}

__global__ __launch_bounds__(NT, 1)
void fused_all(const float* __restrict__ x, const __half* __restrict__ W16,
               const float* __restrict__ qkv_b, const __half* __restrict__ mask16,
               const __half* __restrict__ pw16, const float* __restrict__ bias_p,
               float* __restrict__ out) {
    extern __shared__ char smem[];
    const uint32_t sb = smem_u32(smem);
    const int tid = threadIdx.x, lane = tid & 31, w = tid >> 5;   // w: 0..15
    const int b = blockIdx.x, win = b & (NW - 1);
    const __half* mbase = mask16 + (size_t)win * Nn * Nn;

    const int qrow = lane >> 2;        // 0..7
    const int qc   = (lane & 3) * 2;   // 0,2,4,6
    const int r8 = lane & 7, t4 = lane >> 3;

    // ---- cp.async W sec0 -> B0 (all 512 threads) ----
#pragma unroll
    for (int it = 0; it < 4; ++it) {
        int idx = it * NT + tid;
        int n = idx >> 4, g = idx & 15;
        cp_async16(sb + FSM_B0 + (g >> 3) * 16384 + n * 128 + 16 * ((g & 7) ^ (n & 7)),
                   W16 + (size_t)n * 128 + g * 8);
    }
    CP_COMMIT();

    // ---- x tile -> XA fp16 (all 512 threads) ----
    {
        const float4* A4 = reinterpret_cast<const float4*>(x + (size_t)b * Nn * 128);
#pragma unroll
        for (int it = 0; it < 4; ++it) {
            int idx = it * NT + tid;
            int m = idx >> 4, g = idx & 15;
            float4 a = A4[(size_t)m * 32 + g * 2];
            float4 c = A4[(size_t)m * 32 + g * 2 + 1];
            uint4 u = {pack_h2(a.x, a.y), pack_h2(a.z, a.w),
                       pack_h2(c.x, c.y), pack_h2(c.z, c.w)};
            *reinterpret_cast<uint4*>(
                (char*)smem + FSM_XA + (g >> 3) * 16384 + m * 128 +
                16 * ((g & 7) ^ (m & 7))) = u;
        }
    }
    CP_WAIT0();
    __syncthreads();

    // GEMM warp geometry (phases 1 & 3, warps 0-7 only): 4m x 2n, tile 32x64
    const int wm = w & 3, wn = (w >> 2) & 1;
    const int ga_row0 = wm * 32 + (t4 & 1) * 8 + r8;
    const int ga_us   = t4 >> 1;
    const int gb_roff = (t4 >> 1) * 8 + r8;
    const int gb_us   = t4 & 1;

    // ================= Phase 1: QKV sections (warps 0-7) =================
#pragma unroll
    for (int sec = 0; sec < 3; ++sec) {
        if (sec < 2) {
            const uint32_t sBn = (sec == 0) ? (sb + FSM_VR) : (sb + FSM_B0);
            const __half* Bp = W16 + (size_t)((sec + 1) * 128) * 128;
#pragma unroll
            for (int it = 0; it < 4; ++it) {
                int idx = it * NT + tid;
                int n = idx >> 4, g = idx & 15;
                cp_async16(sBn + (g >> 3) * 16384 + n * 128 + 16 * ((g & 7) ^ (n & 7)),
                           Bp + (size_t)n * 128 + g * 8);
            }
            CP_COMMIT();
        }

        if (w < 8) {
            const uint32_t sB = (sec == 1) ? (sb + FSM_VR) : (sb + FSM_B0);
            float acc[2][8][4];
#pragma unroll
            for (int i = 0; i < 2; ++i)
#pragma unroll
                for (int j = 0; j < 8; ++j)
#pragma unroll
                    for (int k = 0; k < 4; ++k) acc[i][j][k] = 0.f;

            // mainloop: 8 k-steps of k=16
#pragma unroll
            for (int s = 0; s < 8; ++s) {
                const int c = s >> 2;
                const int ku = (s & 3) * 2;
                uint32_t af[2][4], bf[8][2];
#pragma unroll
                for (int mf = 0; mf < 2; ++mf) {
                    int row = ga_row0 + mf * 16;
                    uint32_t addr = sb + FSM_XA + c * 16384 + row * 128 +
                                    (((ku + ga_us) * 16) ^ ((row & 7) * 16));
                    ldsm4(af[mf][0], af[mf][1], af[mf][2], af[mf][3], addr);
                }
#pragma unroll
                for (int p = 0; p < 4; ++p) {
                    int row = wn * 64 + p * 16 + gb_roff;
                    uint32_t addr = sB + c * 16384 + row * 128 +
                                    (((ku + gb_us) * 16) ^ ((row & 7) * 16));
                    ldsm4(bf[p * 2][0], bf[p * 2][1], bf[p * 2 + 1][0],
                          bf[p * 2 + 1][1], addr);
                }
#pragma unroll
                for (int mf = 0; mf < 2; ++mf)
#pragma unroll
                    for (int nf = 0; nf < 8; ++nf)
                        mma_f16(acc[mf][nf], af[mf], bf[nf]);
            }

            // epilogue: + bias, pack fp16, store to head-chunked prow smem
#pragma unroll
            for (int mf = 0; mf < 2; ++mf) {
                const int r0 = wm * 32 + mf * 16 + qrow;
#pragma unroll
                for (int nf = 0; nf < 8; ++nf) {
                    const int col = wn * 64 + nf * 8 + qc;       // 0..127
                    float2 bv = *reinterpret_cast<const float2*>(&qkv_b[sec * 128 + col]);
                    float v00 = acc[mf][nf][0] + bv.x, v01 = acc[mf][nf][1] + bv.y;
                    float v10 = acc[mf][nf][2] + bv.x, v11 = acc[mf][nf][3] + bv.y;
                    const uint32_t hb = (uint32_t)(wn * 2 + (nf >> 2)) * 8192;
                    const uint32_t o0 = hb + prow_addr(r0, nf & 3) + qc * 2;
                    const uint32_t o1 = hb + prow_addr(r0 + 8, nf & 3) + qc * 2;
                    uint32_t p0, p1;
                    if (sec == 0) {
                        p0 = pack_h2(v00 * SCALE, v01 * SCALE);
                        p1 = pack_h2(v10 * SCALE, v11 * SCALE);
                        asm volatile("st.shared.b32 [%0], %1;" :: "r"(sb + FSM_Q + o0), "r"(p0) : "memory");
                        asm volatile("st.shared.b32 [%0], %1;" :: "r"(sb + FSM_Q + o1), "r"(p1) : "memory");
                    } else if (sec == 1) {
                        p0 = pack_h2(v00, v01);
                        p1 = pack_h2(v10, v11);
                        asm volatile("st.shared.b32 [%0], %1;" :: "r"(sb + FSM_KHI + o0), "r"(p0) : "memory");
                        asm volatile("st.shared.b32 [%0], %1;" :: "r"(sb + FSM_KHI + o1), "r"(p1) : "memory");
                        uint32_t l0 = pack_h2_lo(v00, v01);
                        uint32_t l1 = pack_h2_lo(v10, v11);
                        asm volatile("st.shared.b32 [%0], %1;" :: "r"(sb + FSM_KLO + o0), "r"(l0) : "memory");
                        asm volatile("st.shared.b32 [%0], %1;" :: "r"(sb + FSM_KLO + o1), "r"(l1) : "memory");
                    } else {
                        p0 = pack_h2(v00, v01);
                        p1 = pack_h2(v10, v11);
                        asm volatile("st.shared.b32 [%0], %1;" :: "r"(sb + FSM_VR + o0), "r"(p0) : "memory");
                        asm volatile("st.shared.b32 [%0], %1;" :: "r"(sb + FSM_VR + o1), "r"(p1) : "memory");
                    }
                }
            }
        }

        if (sec < 2) CP_WAIT0();
        __syncthreads();
    }

    // ---- prefetch proj weights into (dead) XA region (all threads) ----
#pragma unroll
    for (int it = 0; it < 4; ++it) {
        int idx = it * NT + tid;
        int n = idx >> 4, g = idx & 15;
        cp_async16(sb + FSM_XA + (g >> 3) * 16384 + n * 128 + 16 * ((g & 7) ^ (n & 7)),
                   pw16 + (size_t)n * 128 + g * 8);
    }
    CP_COMMIT();

    // ================= Phase 2: attention, ALL 16 warps ====================
    const int a_us = t4 >> 1, b_us = t4 & 1;
    const int wrow = (w & 7) * 16;                  // warp's 16 q-rows
    const int a_row0 = wrow + (t4 & 1) * 8 + r8;
    const int b_roff = (t4 >> 1) * 8 + r8;

#pragma unroll
    for (int pair = 0; pair < 2; ++pair) {
        const int h = pair * 2 + (w >> 3);          // warp's head this pass
        const uint32_t qb  = sb + FSM_Q   + h * 8192;
        const uint32_t khb = sb + FSM_KHI + h * 8192;
        const uint32_t klb = sb + FSM_KLO + h * 8192;
        const uint32_t vb  = sb + FSM_VR  + h * 8192;

        // Q fragments for this head (8 regs)
        uint32_t qf[2][4];
#pragma unroll
        for (int s = 0; s < 2; ++s)
            ldsm4(qf[s][0], qf[s][1], qf[s][2], qf[s][3],
                  qb + prow_addr(a_row0, s * 2 + a_us));

        // acc init from fp16 mask (gmem; L1-hot after first touch)
        float acc[16][4];
        {
            const __half* mr = mbase + (wrow + qrow) * Nn + qc;
#pragma unroll
            for (int nf = 0; nf < 16; ++nf) {
                float2 f0 = __half22float2(*reinterpret_cast<const __half2*>(mr + nf * 8));
                float2 f1 = __half22float2(*reinterpret_cast<const __half2*>(mr + 8 * Nn + nf * 8));
                acc[nf][0] = f0.x; acc[nf][1] = f0.y;
                acc[nf][2] = f1.x; acc[nf][3] = f1.y;
            }
        }

        // S mma: 2 k-steps (hd=32, k16); hi pass then lo pass per k-step
#pragma unroll
        for (int s = 0; s < 2; ++s) {
            const int ku = s * 2;
#pragma unroll
            for (int p = 0; p < 8; ++p) {
                uint32_t off = prow_addr(p * 16 + b_roff, ku + b_us);
                uint32_t kh[2][2];
                ldsm4(kh[0][0], kh[0][1], kh[1][0], kh[1][1], khb + off);
                mma_f16(acc[p * 2 + 0], qf[s], kh[0]);
                mma_f16(acc[p * 2 + 1], qf[s], kh[1]);
            }
#pragma unroll
            for (int p = 0; p < 8; ++p) {
                uint32_t off = prow_addr(p * 16 + b_roff, ku + b_us);
                uint32_t kl[2][2];
                ldsm4(kl[0][0], kl[0][1], kl[1][0], kl[1][1], klb + off);
                mma_f16(acc[p * 2 + 0], qf[s], kl[0]);
                mma_f16(acc[p * 2 + 1], qf[s], kl[1]);
            }
        }

        // register softmax — TREE reductions
        float inv[2];
#pragma unroll
        for (int hf = 0; hf < 2; ++hf) {
            float t[16];
#pragma unroll
            for (int nf = 0; nf < 16; ++nf)
                t[nf] = fmaxf(acc[nf][hf * 2], acc[nf][hf * 2 + 1]);
#pragma unroll
            for (int st = 8; st > 0; st >>= 1)
#pragma unroll
                for (int i = 0; i < 16; ++i)
                    if (i < st) t[i] = fmaxf(t[i], t[i + st]);
            float mx = fmaxf(t[0], __shfl_xor_sync(0xffffffffu, t[0], 1));
            mx = fmaxf(mx, __shfl_xor_sync(0xffffffffu, mx, 2));

#pragma unroll
            for (int nf = 0; nf < 16; ++nf) {
                float e0 = __expf(acc[nf][hf * 2] - mx);
                float e1 = __expf(acc[nf][hf * 2 + 1] - mx);
                acc[nf][hf * 2] = e0;
                acc[nf][hf * 2 + 1] = e1;
                t[nf] = e0 + e1;
            }
#pragma unroll
            for (int st = 8; st > 0; st >>= 1)
#pragma unroll
                for (int i = 0; i < 16; ++i)
                    if (i < st) t[i] += t[i + st];
            float sum = t[0] + __shfl_xor_sync(0xffffffffu, t[0], 1);
            sum += __shfl_xor_sync(0xffffffffu, sum, 2);
            inv[hf] = 1.f / sum;
        }

        // PV mma: P straight from registers (FA2 repack)
        float o[4][4];
#pragma unroll
        for (int j = 0; j < 4; ++j)
#pragma unroll
            for (int k = 0; k < 4; ++k) o[j][k] = 0.f;

#pragma unroll
        for (int s2 = 0; s2 < 8; ++s2) {
            uint32_t pf[4] = {
                pack_h2(acc[2 * s2][0],     acc[2 * s2][1]),
                pack_h2(acc[2 * s2][2],     acc[2 * s2][3]),
                pack_h2(acc[2 * s2 + 1][0], acc[2 * s2 + 1][1]),
                pack_h2(acc[2 * s2 + 1][2], acc[2 * s2 + 1][3])};
            uint32_t vf[4][2];
            const int jrow = s2 * 16 + (t4 & 1) * 8 + r8;
#pragma unroll
            for (int nu = 0; nu < 2; ++nu) {
                ldsm4t(vf[nu * 2][0], vf[nu * 2][1], vf[nu * 2 + 1][0],
                       vf[nu * 2 + 1][1], vb + prow_addr(jrow, nu * 2 + (t4 >> 1)));
            }
#pragma unroll
            for (int nf = 0; nf < 4; ++nf)
                mma_f16(o[nf], pf, vf[nf]);
        }

        // O -> ATT tile (overlay B0), GEMM-A swizzled layout, normalized fp16
        {
            const int r0 = wrow + qrow;
#pragma unroll
            for (int nf = 0; nf < 4; ++nf) {
                int g = h * 4 + nf;              // 16B col unit 0..15
                uint32_t baseu = sb + FSM_B0 + (g >> 3) * 16384;
                uint32_t a0 = baseu + r0 * 128 + 16 * ((g & 7) ^ (r0 & 7)) + qc * 2;
                int r1 = r0 + 8;
                uint32_t a1 = baseu + r1 * 128 + 16 * ((g & 7) ^ (r1 & 7)) + qc * 2;
                uint32_t p0 = pack_h2(o[nf][0] * inv[0], o[nf][1] * inv[0]);
                uint32_t p1 = pack_h2(o[nf][2] * inv[1], o[nf][3] * inv[1]);
                asm volatile("st.shared.b32 [%0], %1;" :: "r"(a0), "r"(p0) : "memory");
                asm volatile("st.shared.b32 [%0], %1;" :: "r"(a1), "r"(p1) : "memory");
            }
        }
    }

    CP_WAIT0();        // PW arrived
    __syncthreads();   // ATT complete

    // ================= Phase 3: proj GEMM (warps 0-7) =================
    if (w < 8) {
        float acc[2][8][4];
#pragma unroll
        for (int i = 0; i < 2; ++i)
#pragma unroll
            for (int j = 0; j < 8; ++j)
#pragma unroll
                for (int k = 0; k < 4; ++k) acc[i][j][k] = 0.f;

#pragma unroll
        for (int s = 0; s < 8; ++s) {
            const int c = s >> 2;
            const int ku = (s & 3) * 2;
            uint32_t af[2][4], bf[8][2];
#pragma unroll
            for (int mf = 0; mf < 2; ++mf) {
                int row = ga_row0 + mf * 16;
                uint32_t addr = sb + FSM_B0 + c * 16384 + row * 128 +
                                (((ku + ga_us) * 16) ^ ((row & 7) * 16));
                ldsm4(af[mf][0], af[mf][1], af[mf][2], af[mf][3], addr);
            }
#pragma unroll
            for (int p = 0; p < 4; ++p) {
                int row = wn * 64 + p * 16 + gb_roff;
                uint32_t addr = sb + FSM_XA + c * 16384 + row * 128 +
                                (((ku + gb_us) * 16) ^ ((row & 7) * 16));
                ldsm4(bf[p * 2][0], bf[p * 2][1], bf[p * 2 + 1][0],
                      bf[p * 2 + 1][1], addr);
            }
#pragma unroll
            for (int mf = 0; mf < 2; ++mf)
#pragma unroll
                for (int nf = 0; nf < 8; ++nf)
                    mma_f16(acc[mf][nf], af[mf], bf[nf]);
        }

#pragma unroll
        for (int mf = 0; mf < 2; ++mf) {
            const int rowg = b * 128 + wm * 32 + mf * 16 + qrow;
#pragma unroll
            for (int nf = 0; nf < 8; ++nf) {
                const int col = wn * 64 + nf * 8 + qc;
                float2 bv = *reinterpret_cast<const float2*>(&bias_p[col]);
                float2 o0 = {acc[mf][nf][0] + bv.x, acc[mf][nf][1] + bv.y};
                float2 o1 = {acc[mf][nf][2] + bv.x, acc[mf][nf][3] + bv.y};
                *reinterpret_cast<float2*>(out + (size_t)rowg * 128 + col) = o0;
                *reinterpret_cast<float2*>(out + (size_t)(rowg + 8) * 128 + col) = o1;
            }
        }
    }
}

// ---------------------------------------------------------------------------
// Launch
// ---------------------------------------------------------------------------
extern "C" void kernel_launch(void* const* d_in, const int* in_sizes, int n_in,
                              void* d_out, int out_size) {
    const float* x      = (const float*)d_in[0];
    const float* mask   = (const float*)d_in[1];
    const float* qkv_w  = (const float*)d_in[2];
    const float* qkv_b  = (const float*)d_in[3];
    const float* proj_w = (const float*)d_in[4];
    const float* proj_b = (const float*)d_in[5];
    float* out = (float*)d_out;

    __half *p_w16, *p_pw16, *p_mask16;
    cudaGetSymbolAddress((void**)&p_w16, g_w16);
    cudaGetSymbolAddress((void**)&p_pw16, g_pw16);
    cudaGetSymbolAddress((void**)&p_mask16, g_mask16);

    cudaFuncSetAttribute(fused_all, cudaFuncAttributeMaxDynamicSharedMemorySize,
                         FSM_TOTAL);

    // 0) fp16 prepass (weights + mask)
    prep16<<<(PREP_TOT + 255) / 256, 256>>>(mask, qkv_w, proj_w);

    // 1) fully fused QKV + attention + proj; hybrid 512-thread CTA per window
    fused_all<<<Bb, NT, FSM_TOTAL>>>(x, p_w16, qkv_b, p_mask16, p_pw16,
                                     proj_b, out);
}

// round 15
// speedup vs baseline: 1.1873x; 1.1873x over previous
#include <cuda_runtime.h>
#include <cuda_fp16.h>
#include <cstdint>

// Problem constants
#define Bb   2048
#define Nn   128
#define Cc   128
#define Hh   4
#define NW   64
#define M_TOT (Bb * Nn)
#define SCALE 0.1767766952966369f  // 1/sqrt(32)
#define NSM  148                   // persistent grid size

// ---------------------------------------------------------------------------
// Helpers (baseline ISA: ldmatrix + mma.sync fp16 + cp.async)
// ---------------------------------------------------------------------------
__device__ __forceinline__ uint32_t smem_u32(const void* p) {
    uint32_t a;
    asm("{ .reg .u64 t; cvta.to.shared.u64 t, %1; cvt.u32.u64 %0, t; }"
        : "=r"(a) : "l"(p));
    return a;
}
__device__ __forceinline__ uint32_t pack_h2(float a, float b) {
    __half2 h = __floats2half2_rn(a, b);
    return *reinterpret_cast<uint32_t*>(&h);
}
__device__ __forceinline__ uint32_t pack_h2_lo(float a, float b) {
    float ah = __half2float(__float2half_rn(a));
    float bh = __half2float(__float2half_rn(b));
    return pack_h2(a - ah, b - bh);
}
__device__ __forceinline__ void ldsm4(uint32_t& r0, uint32_t& r1, uint32_t& r2,
                                      uint32_t& r3, uint32_t addr) {
    asm volatile("ldmatrix.sync.aligned.m8n8.x4.shared.b16 {%0,%1,%2,%3}, [%4];"
                 : "=r"(r0), "=r"(r1), "=r"(r2), "=r"(r3) : "r"(addr));
}
__device__ __forceinline__ void ldsm4t(uint32_t& r0, uint32_t& r1, uint32_t& r2,
                                       uint32_t& r3, uint32_t addr) {
    asm volatile("ldmatrix.sync.aligned.m8n8.x4.trans.shared.b16 {%0,%1,%2,%3}, [%4];"
                 : "=r"(r0), "=r"(r1), "=r"(r2), "=r"(r3) : "r"(addr));
}
__device__ __forceinline__ void mma_f16(float* c, const uint32_t* a,
                                        const uint32_t* b) {
    asm volatile(
        "mma.sync.aligned.m16n8k16.row.col.f32.f16.f16.f32 "
        "{%0,%1,%2,%3}, {%4,%5,%6,%7}, {%8,%9}, {%0,%1,%2,%3};"
        : "+f"(c[0]), "+f"(c[1]), "+f"(c[2]), "+f"(c[3])
        : "r"(a[0]), "r"(a[1]), "r"(a[2]), "r"(a[3]), "r"(b[0]), "r"(b[1]));
}
__device__ __forceinline__ void cp_async16(uint32_t saddr, const void* gaddr) {
    asm volatile("cp.async.cg.shared.global [%0], [%1], 16;"
                 :: "r"(saddr), "l"(gaddr));
}
#define CP_COMMIT() asm volatile("cp.async.commit_group;" ::: "memory")
#define CP_WAIT0()  asm volatile("cp.async.wait_group 0;" ::: "memory")

// ---------------------------------------------------------------------------
// Scratch
// ---------------------------------------------------------------------------
__device__ __half g_w16[3 * Cc * Cc];
__device__ __half g_pw16[Cc * Cc];
__device__ __half g_mask16[NW * Nn * Nn];

// ---------------------------------------------------------------------------
// Prepass: weights + mask -> fp16
// ---------------------------------------------------------------------------
#define MASK2  (NW * Nn * Nn / 2)
#define QW2    (3 * Cc * Cc / 2)
#define PW2    (Cc * Cc / 2)
#define PREP_TOT (MASK2 + QW2 + PW2)

__global__ void prep16(const float* __restrict__ mask,
                       const float* __restrict__ qkv_w,
                       const float* __restrict__ proj_w) {
    int idx = blockIdx.x * blockDim.x + threadIdx.x;
    if (idx >= PREP_TOT) return;
    if (idx < MASK2) {
        float2 v = reinterpret_cast<const float2*>(mask)[idx];
        reinterpret_cast<uint32_t*>(g_mask16)[idx] = pack_h2(v.x, v.y);
    } else if (idx < MASK2 + QW2) {
        float2 v = reinterpret_cast<const float2*>(qkv_w)[idx - MASK2];
        reinterpret_cast<uint32_t*>(g_w16)[idx - MASK2] = pack_h2(v.x, v.y);
    } else {
        float2 v = reinterpret_cast<const float2*>(proj_w)[idx - MASK2 - QW2];
        reinterpret_cast<uint32_t*>(g_pw16)[idx - MASK2 - QW2] = pack_h2(v.x, v.y);
    }
}

// ---------------------------------------------------------------------------
// FULLY FUSED PERSISTENT kernel (256 threads / 8 warps, 1 CTA/SM, grid=148).
// Each CTA loops over windows b = blockIdx.x + 148*i  (R13 body per window).
// R13 features retained: A-frag register cache across QKV sections, Q-frag
// prefetch for all heads, mask register cache, tree softmax, register-
// repacked PV, cp.async W ping-pong, all tiles smem-resident.
// smem: XA/PW 32K | B0/ATT 32K | Q 32K | KHI 32K | KLO 32K | VR/V 32K =192KB.
// ---------------------------------------------------------------------------
#define FSM_XA   0
#define FSM_B0   32768
#define FSM_Q    65536
#define FSM_KHI  98304
#define FSM_KLO  131072
#define FSM_VR   163840
#define FSM_TOTAL 196608

__device__ __forceinline__ uint32_t prow_addr(int r, int u) {
    return (uint32_t)((r >> 1) * 128 + 16 * ((((r & 1) * 4) + u) ^ ((r >> 1) & 7)));
}

__global__ __launch_bounds__(256, 1)
void fused_all(const float* __restrict__ x, const __half* __restrict__ W16,
               const float* __restrict__ qkv_b, const __half* __restrict__ mask16,
               const __half* __restrict__ pw16, const float* __restrict__ bias_p,
               float* __restrict__ out) {
    extern __shared__ char smem[];
    const uint32_t sb = smem_u32(smem);
    const int tid = threadIdx.x, lane = tid & 31, w = tid >> 5;   // w: 0..7

    const int qrow = lane >> 2;        // 0..7
    const int qc   = (lane & 3) * 2;   // 0,2,4,6
    const int r8 = lane & 7, t4 = lane >> 3;

    // GEMM warp geometry (QKV + proj phases): 4m x 2n, warp tile 32x64
    const int wm = w & 3, wn = w >> 2;
    const int ga_row0 = wm * 32 + (t4 & 1) * 8 + r8;
    const int ga_us   = t4 >> 1;
    const int gb_roff = (t4 >> 1) * 8 + r8;
    const int gb_us   = t4 & 1;

    // attention warp geometry
    const int a_us = t4 >> 1, b_us = t4 & 1;
    const int a_row0 = w * 16 + (t4 & 1) * 8 + r8;   // warp owns 16 q-rows
    const int b_roff = (t4 >> 1) * 8 + r8;

    for (int b = blockIdx.x; b < Bb; b += NSM) {
        const int win = b & (NW - 1);
        const __half* mbase = mask16 + (size_t)win * Nn * Nn;

        // ---- cp.async W sec0 -> B0 ----
#pragma unroll
        for (int it = 0; it < 8; ++it) {
            int idx = it * 256 + tid;
            int n = idx >> 4, g = idx & 15;
            cp_async16(sb + FSM_B0 + (g >> 3) * 16384 + n * 128 + 16 * ((g & 7) ^ (n & 7)),
                       W16 + (size_t)n * 128 + g * 8);
        }
        CP_COMMIT();

        // ---- x tile -> XA fp16 ----
        {
            const float4* A4 = reinterpret_cast<const float4*>(x + (size_t)b * Nn * 128);
#pragma unroll
            for (int it = 0; it < 8; ++it) {
                int idx = it * 256 + tid;
                int m = idx >> 4, g = idx & 15;
                float4 a = A4[(size_t)m * 32 + g * 2];
                float4 c = A4[(size_t)m * 32 + g * 2 + 1];
                uint4 u = {pack_h2(a.x, a.y), pack_h2(a.z, a.w),
                           pack_h2(c.x, c.y), pack_h2(c.z, c.w)};
                *reinterpret_cast<uint4*>(
                    (char*)smem + FSM_XA + (g >> 3) * 16384 + m * 128 +
                    16 * ((g & 7) ^ (m & 7))) = u;
            }
        }
        CP_WAIT0();
        __syncthreads();

        // ---- A-fragments loaded ONCE, reused across all 3 sections ----
        uint32_t af_all[8][2][4];
#pragma unroll
        for (int s = 0; s < 8; ++s) {
            const int c = s >> 2;
            const int ku = (s & 3) * 2;
#pragma unroll
            for (int mf = 0; mf < 2; ++mf) {
                int row = ga_row0 + mf * 16;
                uint32_t addr = sb + FSM_XA + c * 16384 + row * 128 +
                                (((ku + ga_us) * 16) ^ ((row & 7) * 16));
                ldsm4(af_all[s][mf][0], af_all[s][mf][1], af_all[s][mf][2],
                      af_all[s][mf][3], addr);
            }
        }

        // ================= Phase 1: QKV sections =================
#pragma unroll
        for (int sec = 0; sec < 3; ++sec) {
            if (sec < 2) {
                const uint32_t sBn = (sec == 0) ? (sb + FSM_VR) : (sb + FSM_B0);
                const __half* Bp = W16 + (size_t)((sec + 1) * 128) * 128;
#pragma unroll
                for (int it = 0; it < 8; ++it) {
                    int idx = it * 256 + tid;
                    int n = idx >> 4, g = idx & 15;
                    cp_async16(sBn + (g >> 3) * 16384 + n * 128 + 16 * ((g & 7) ^ (n & 7)),
                               Bp + (size_t)n * 128 + g * 8);
                }
                CP_COMMIT();
            }

            const uint32_t sB = (sec == 1) ? (sb + FSM_VR) : (sb + FSM_B0);
            float acc[2][8][4];
#pragma unroll
            for (int i = 0; i < 2; ++i)
#pragma unroll
                for (int j = 0; j < 8; ++j)
#pragma unroll
                    for (int k = 0; k < 4; ++k) acc[i][j][k] = 0.f;

            // mainloop: 8 k-steps of k=16 (A from registers)
#pragma unroll
            for (int s = 0; s < 8; ++s) {
                const int c = s >> 2;
                const int ku = (s & 3) * 2;
                uint32_t bf[8][2];
#pragma unroll
                for (int p = 0; p < 4; ++p) {
                    int row = wn * 64 + p * 16 + gb_roff;
                    uint32_t addr = sB + c * 16384 + row * 128 +
                                    (((ku + gb_us) * 16) ^ ((row & 7) * 16));
                    ldsm4(bf[p * 2][0], bf[p * 2][1], bf[p * 2 + 1][0],
                          bf[p * 2 + 1][1], addr);
                }
#pragma unroll
                for (int mf = 0; mf < 2; ++mf)
#pragma unroll
                    for (int nf = 0; nf < 8; ++nf)
                        mma_f16(acc[mf][nf], af_all[s][mf], bf[nf]);
            }

            // epilogue: + bias, pack fp16, store to head-chunked prow smem
#pragma unroll
            for (int mf = 0; mf < 2; ++mf) {
                const int r0 = wm * 32 + mf * 16 + qrow;
#pragma unroll
                for (int nf = 0; nf < 8; ++nf) {
                    const int col = wn * 64 + nf * 8 + qc;       // 0..127
                    float2 bv = *reinterpret_cast<const float2*>(&qkv_b[sec * 128 + col]);
                    float v00 = acc[mf][nf][0] + bv.x, v01 = acc[mf][nf][1] + bv.y;
                    float v10 = acc[mf][nf][2] + bv.x, v11 = acc[mf][nf][3] + bv.y;
                    const uint32_t hb = (uint32_t)(wn * 2 + (nf >> 2)) * 8192;
                    const uint32_t o0 = hb + prow_addr(r0, nf & 3) + qc * 2;
                    const uint32_t o1 = hb + prow_addr(r0 + 8, nf & 3) + qc * 2;
                    uint32_t p0, p1;
                    if (sec == 0) {
                        p0 = pack_h2(v00 * SCALE, v01 * SCALE);
                        p1 = pack_h2(v10 * SCALE, v11 * SCALE);
                        asm volatile("st.shared.b32 [%0], %1;" :: "r"(sb + FSM_Q + o0), "r"(p0) : "memory");
                        asm volatile("st.shared.b32 [%0], %1;" :: "r"(sb + FSM_Q + o1), "r"(p1) : "memory");
                    } else if (sec == 1) {
                        p0 = pack_h2(v00, v01);
                        p1 = pack_h2(v10, v11);
                        asm volatile("st.shared.b32 [%0], %1;" :: "r"(sb + FSM_KHI + o0), "r"(p0) : "memory");
                        asm volatile("st.shared.b32 [%0], %1;" :: "r"(sb + FSM_KHI + o1), "r"(p1) : "memory");
                        uint32_t l0 = pack_h2_lo(v00, v01);
                        uint32_t l1 = pack_h2_lo(v10, v11);
                        asm volatile("st.shared.b32 [%0], %1;" :: "r"(sb + FSM_KLO + o0), "r"(l0) : "memory");
                        asm volatile("st.shared.b32 [%0], %1;" :: "r"(sb + FSM_KLO + o1), "r"(l1) : "memory");
                    } else {
                        p0 = pack_h2(v00, v01);
                        p1 = pack_h2(v10, v11);
                        asm volatile("st.shared.b32 [%0], %1;" :: "r"(sb + FSM_VR + o0), "r"(p0) : "memory");
                        asm volatile("st.shared.b32 [%0], %1;" :: "r"(sb + FSM_VR + o1), "r"(p1) : "memory");
                    }
                }
            }

            if (sec < 2) CP_WAIT0();
            __syncthreads();
        }

        // ---- prefetch proj weights into (dead) XA region ----
#pragma unroll
        for (int it = 0; it < 8; ++it) {
            int idx = it * 256 + tid;
            int n = idx >> 4, g = idx & 15;
            cp_async16(sb + FSM_XA + (g >> 3) * 16384 + n * 128 + 16 * ((g & 7) ^ (n & 7)),
                       pw16 + (size_t)n * 128 + g * 8);
        }
        CP_COMMIT();

        // ---- mask -> registers (head-invariant; packed fp16; L2-hot) ----
        uint32_t mreg[16][2];
        {
            const __half* mr = mbase + (w * 16 + qrow) * Nn + qc;
#pragma unroll
            for (int nf = 0; nf < 16; ++nf) {
                mreg[nf][0] = *reinterpret_cast<const uint32_t*>(mr + nf * 8);
                mreg[nf][1] = *reinterpret_cast<const uint32_t*>(mr + 8 * Nn + nf * 8);
            }
        }

        // ================= Phase 2: attention (no syncs in head loop) ======
        // all heads' Q fragments prefetched (8 ldsm4, 32 regs)
        uint32_t qf_all[Hh][2][4];
#pragma unroll
        for (int h = 0; h < Hh; ++h)
#pragma unroll
            for (int s = 0; s < 2; ++s)
                ldsm4(qf_all[h][s][0], qf_all[h][s][1], qf_all[h][s][2],
                      qf_all[h][s][3],
                      sb + FSM_Q + h * 8192 + prow_addr(a_row0, s * 2 + a_us));

#pragma unroll
        for (int h = 0; h < Hh; ++h) {
            const uint32_t khb = sb + FSM_KHI + h * 8192;
            const uint32_t klb = sb + FSM_KLO + h * 8192;
            const uint32_t vb  = sb + FSM_VR  + h * 8192;

            // acc init from register mask cache
            float acc[16][4];
#pragma unroll
            for (int nf = 0; nf < 16; ++nf) {
                float2 f0 = __half22float2(*reinterpret_cast<const __half2*>(&mreg[nf][0]));
                float2 f1 = __half22float2(*reinterpret_cast<const __half2*>(&mreg[nf][1]));
                acc[nf][0] = f0.x; acc[nf][1] = f0.y;
                acc[nf][2] = f1.x; acc[nf][3] = f1.y;
            }

            // S mma: 2 k-steps; hi pass then lo pass per k-step
#pragma unroll
            for (int s = 0; s < 2; ++s) {
                const int ku = s * 2;
#pragma unroll
                for (int p = 0; p < 8; ++p) {
                    uint32_t off = prow_addr(p * 16 + b_roff, ku + b_us);
                    uint32_t kh[2][2];
                    ldsm4(kh[0][0], kh[0][1], kh[1][0], kh[1][1], khb + off);
                    mma_f16(acc[p * 2 + 0], qf_all[h][s], kh[0]);
                    mma_f16(acc[p * 2 + 1], qf_all[h][s], kh[1]);
                }
#pragma unroll
                for (int p = 0; p < 8; ++p) {
                    uint32_t off = prow_addr(p * 16 + b_roff, ku + b_us);
                    uint32_t kl[2][2];
                    ldsm4(kl[0][0], kl[0][1], kl[1][0], kl[1][1], klb + off);
                    mma_f16(acc[p * 2 + 0], qf_all[h][s], kl[0]);
                    mma_f16(acc[p * 2 + 1], qf_all[h][s], kl[1]);
                }
            }

            // register softmax — TREE reductions
            float inv[2];
#pragma unroll
            for (int hf = 0; hf < 2; ++hf) {
                float t[16];
#pragma unroll
                for (int nf = 0; nf < 16; ++nf)
                    t[nf] = fmaxf(acc[nf][hf * 2], acc[nf][hf * 2 + 1]);
#pragma unroll
                for (int st = 8; st > 0; st >>= 1)
#pragma unroll
                    for (int i = 0; i < 16; ++i)
                        if (i < st) t[i] = fmaxf(t[i], t[i + st]);
                float mx = fmaxf(t[0], __shfl_xor_sync(0xffffffffu, t[0], 1));
                mx = fmaxf(mx, __shfl_xor_sync(0xffffffffu, mx, 2));

#pragma unroll
                for (int nf = 0; nf < 16; ++nf) {
                    float e0 = __expf(acc[nf][hf * 2] - mx);
                    float e1 = __expf(acc[nf][hf * 2 + 1] - mx);
                    acc[nf][hf * 2] = e0;
                    acc[nf][hf * 2 + 1] = e1;
                    t[nf] = e0 + e1;
                }
#pragma unroll
                for (int st = 8; st > 0; st >>= 1)
#pragma unroll
                    for (int i = 0; i < 16; ++i)
                        if (i < st) t[i] += t[i + st];
                float sum = t[0] + __shfl_xor_sync(0xffffffffu, t[0], 1);
                sum += __shfl_xor_sync(0xffffffffu, sum, 2);
                inv[hf] = 1.f / sum;
            }

            // PV mma: P straight from registers (FA2 repack)
            float o[4][4];
#pragma unroll
            for (int j = 0; j < 4; ++j)
#pragma unroll
                for (int k = 0; k < 4; ++k) o[j][k] = 0.f;

#pragma unroll
            for (int s2 = 0; s2 < 8; ++s2) {
                uint32_t pf[4] = {
                    pack_h2(acc[2 * s2][0],     acc[2 * s2][1]),
                    pack_h2(acc[2 * s2][2],     acc[2 * s2][3]),
                    pack_h2(acc[2 * s2 + 1][0], acc[2 * s2 + 1][1]),
                    pack_h2(acc[2 * s2 + 1][2], acc[2 * s2 + 1][3])};
                uint32_t vf[4][2];
                const int jrow = s2 * 16 + (t4 & 1) * 8 + r8;
#pragma unroll
                for (int nu = 0; nu < 2; ++nu) {
                    ldsm4t(vf[nu * 2][0], vf[nu * 2][1], vf[nu * 2 + 1][0],
                           vf[nu * 2 + 1][1], vb + prow_addr(jrow, nu * 2 + (t4 >> 1)));
                }
#pragma unroll
                for (int nf = 0; nf < 4; ++nf)
                    mma_f16(o[nf], pf, vf[nf]);
            }

            // O -> ATT tile (overlay B0), GEMM-A swizzled layout, fp16
            {
                const int r0 = w * 16 + qrow;
#pragma unroll
                for (int nf = 0; nf < 4; ++nf) {
                    int g = h * 4 + nf;              // 16B col unit 0..15
                    uint32_t baseu = sb + FSM_B0 + (g >> 3) * 16384;
                    uint32_t a0 = baseu + r0 * 128 + 16 * ((g & 7) ^ (r0 & 7)) + qc * 2;
                    int r1 = r0 + 8;
                    uint32_t a1 = baseu + r1 * 128 + 16 * ((g & 7) ^ (r1 & 7)) + qc * 2;
                    uint32_t p0 = pack_h2(o[nf][0] * inv[0], o[nf][1] * inv[0]);
                    uint32_t p1 = pack_h2(o[nf][2] * inv[1], o[nf][3] * inv[1]);
                    asm volatile("st.shared.b32 [%0], %1;" :: "r"(a0), "r"(p0) : "memory");
                    asm volatile("st.shared.b32 [%0], %1;" :: "r"(a1), "r"(p1) : "memory");
                }
            }
        }

        CP_WAIT0();        // PW arrived
        __syncthreads();   // ATT complete

        // ================= Phase 3: proj GEMM from smem =================
        {
            float acc[2][8][4];
#pragma unroll
            for (int i = 0; i < 2; ++i)
#pragma unroll
                for (int j = 0; j < 8; ++j)
#pragma unroll
                    for (int k = 0; k < 4; ++k) acc[i][j][k] = 0.f;

#pragma unroll
            for (int s = 0; s < 8; ++s) {
                const int c = s >> 2;
                const int ku = (s & 3) * 2;
                uint32_t af[2][4], bf[8][2];
#pragma unroll
                for (int mf = 0; mf < 2; ++mf) {
                    int row = ga_row0 + mf * 16;
                    uint32_t addr = sb + FSM_B0 + c * 16384 + row * 128 +
                                    (((ku + ga_us) * 16) ^ ((row & 7) * 16));
                    ldsm4(af[mf][0], af[mf][1], af[mf][2], af[mf][3], addr);
                }
#pragma unroll
                for (int p = 0; p < 4; ++p) {
                    int row = wn * 64 + p * 16 + gb_roff;
                    uint32_t addr = sb + FSM_XA + c * 16384 + row * 128 +
                                    (((ku + gb_us) * 16) ^ ((row & 7) * 16));
                    ldsm4(bf[p * 2][0], bf[p * 2][1], bf[p * 2 + 1][0],
                          bf[p * 2 + 1][1], addr);
                }
#pragma unroll
                for (int mf = 0; mf < 2; ++mf)
#pragma unroll
                    for (int nf = 0; nf < 8; ++nf)
                        mma_f16(acc[mf][nf], af[mf], bf[nf]);
            }

#pragma unroll
            for (int mf = 0; mf < 2; ++mf) {
                const int rowg = b * 128 + wm * 32 + mf * 16 + qrow;
#pragma unroll
                for (int nf = 0; nf < 8; ++nf) {
                    const int col = wn * 64 + nf * 8 + qc;
                    float2 bv = *reinterpret_cast<const float2*>(&bias_p[col]);
                    float2 o0 = {acc[mf][nf][0] + bv.x, acc[mf][nf][1] + bv.y};
                    float2 o1 = {acc[mf][nf][2] + bv.x, acc[mf][nf][3] + bv.y};
                    *reinterpret_cast<float2*>(out + (size_t)rowg * 128 + col) = o0;
                    *reinterpret_cast<float2*>(out + (size_t)(rowg + 8) * 128 + col) = o1;
                }
            }
        }

        // smem reads of this window done before next iteration's cp.async
        __syncthreads();
    }
}

// ---------------------------------------------------------------------------
// Launch
// ---------------------------------------------------------------------------
extern "C" void kernel_launch(void* const* d_in, const int* in_sizes, int n_in,
                              void* d_out, int out_size) {
    const float* x      = (const float*)d_in[0];
    const float* mask   = (const float*)d_in[1];
    const float* qkv_w  = (const float*)d_in[2];
    const float* qkv_b  = (const float*)d_in[3];
    const float* proj_w = (const float*)d_in[4];
    const float* proj_b = (const float*)d_in[5];
    float* out = (float*)d_out;

    __half *p_w16, *p_pw16, *p_mask16;
    cudaGetSymbolAddress((void**)&p_w16, g_w16);
    cudaGetSymbolAddress((void**)&p_pw16, g_pw16);
    cudaGetSymbolAddress((void**)&p_mask16, g_mask16);

    cudaFuncSetAttribute(fused_all, cudaFuncAttributeMaxDynamicSharedMemorySize,
                         FSM_TOTAL);

    // 0) fp16 prepass (weights + mask)
    prep16<<<(PREP_TOT + 255) / 256, 256>>>(mask, qkv_w, proj_w);

    // 1) fully fused persistent kernel: 148 CTAs loop over 2048 windows
    fused_all<<<NSM, 256, FSM_TOTAL>>>(x, p_w16, qkv_b, p_mask16, p_pw16,
                                       proj_b, out);
}

// round 16
// speedup vs baseline: 1.2065x; 1.0161x over previous
#include <cuda_runtime.h>
#include <cuda_fp16.h>
#include <cstdint>

// Problem constants
#define Bb   2048
#define Nn   128
#define Cc   128
#define Hh   4
#define NW   64
#define M_TOT (Bb * Nn)
#define SCALE 0.1767766952966369f  // 1/sqrt(32)
#define NSM  148                   // persistent grid size

// ---------------------------------------------------------------------------
// Helpers (baseline ISA: ldmatrix + mma.sync fp16 + cp.async)
// ---------------------------------------------------------------------------
__device__ __forceinline__ uint32_t smem_u32(const void* p) {
    uint32_t a;
    asm("{ .reg .u64 t; cvta.to.shared.u64 t, %1; cvt.u32.u64 %0, t; }"
        : "=r"(a) : "l"(p));
    return a;
}
__device__ __forceinline__ uint32_t pack_h2(float a, float b) {
    __half2 h = __floats2half2_rn(a, b);
    return *reinterpret_cast<uint32_t*>(&h);
}
__device__ __forceinline__ uint32_t pack_h2_lo(float a, float b) {
    float ah = __half2float(__float2half_rn(a));
    float bh = __half2float(__float2half_rn(b));
    return pack_h2(a - ah, b - bh);
}
__device__ __forceinline__ void ldsm4(uint32_t& r0, uint32_t& r1, uint32_t& r2,
                                      uint32_t& r3, uint32_t addr) {
    asm volatile("ldmatrix.sync.aligned.m8n8.x4.shared.b16 {%0,%1,%2,%3}, [%4];"
                 : "=r"(r0), "=r"(r1), "=r"(r2), "=r"(r3) : "r"(addr));
}
__device__ __forceinline__ void ldsm4t(uint32_t& r0, uint32_t& r1, uint32_t& r2,
                                       uint32_t& r3, uint32_t addr) {
    asm volatile("ldmatrix.sync.aligned.m8n8.x4.trans.shared.b16 {%0,%1,%2,%3}, [%4];"
                 : "=r"(r0), "=r"(r1), "=r"(r2), "=r"(r3) : "r"(addr));
}
__device__ __forceinline__ void mma_f16(float* c, const uint32_t* a,
                                        const uint32_t* b) {
    asm volatile(
        "mma.sync.aligned.m16n8k16.row.col.f32.f16.f16.f32 "
        "{%0,%1,%2,%3}, {%4,%5,%6,%7}, {%8,%9}, {%0,%1,%2,%3};"
        : "+f"(c[0]), "+f"(c[1]), "+f"(c[2]), "+f"(c[3])
        : "r"(a[0]), "r"(a[1]), "r"(a[2]), "r"(a[3]), "r"(b[0]), "r"(b[1]));
}
__device__ __forceinline__ void cp_async16(uint32_t saddr, const void* gaddr) {
    asm volatile("cp.async.cg.shared.global [%0], [%1], 16;"
                 :: "r"(saddr), "l"(gaddr));
}
#define CP_COMMIT() asm volatile("cp.async.commit_group;" ::: "memory")
#define CP_WAIT0()  asm volatile("cp.async.wait_group 0;" ::: "memory")
#define CP_WAIT1()  asm volatile("cp.async.wait_group 1;" ::: "memory")

// ---------------------------------------------------------------------------
// Scratch
// ---------------------------------------------------------------------------
__device__ __half g_w16[3 * Cc * Cc];
__device__ __half g_pw16[Cc * Cc];
__device__ __half g_mask16[NW * Nn * Nn];

// ---------------------------------------------------------------------------
// Prepass: weights + mask -> fp16
// ---------------------------------------------------------------------------
#define MASK2  (NW * Nn * Nn / 2)
#define QW2    (3 * Cc * Cc / 2)
#define PW2    (Cc * Cc / 2)
#define PREP_TOT (MASK2 + QW2 + PW2)

__global__ void prep16(const float* __restrict__ mask,
                       const float* __restrict__ qkv_w,
                       const float* __restrict__ proj_w) {
    int idx = blockIdx.x * blockDim.x + threadIdx.x;
    if (idx >= PREP_TOT) return;
    if (idx < MASK2) {
        float2 v = reinterpret_cast<const float2*>(mask)[idx];
        reinterpret_cast<uint32_t*>(g_mask16)[idx] = pack_h2(v.x, v.y);
    } else if (idx < MASK2 + QW2) {
        float2 v = reinterpret_cast<const float2*>(qkv_w)[idx - MASK2];
        reinterpret_cast<uint32_t*>(g_w16)[idx - MASK2] = pack_h2(v.x, v.y);
    } else {
        float2 v = reinterpret_cast<const float2*>(proj_w)[idx - MASK2 - QW2];
        reinterpret_cast<uint32_t*>(g_pw16)[idx - MASK2 - QW2] = pack_h2(v.x, v.y);
    }
}

// ---------------------------------------------------------------------------
// FULLY FUSED PERSISTENT kernel with cross-window prefetch pipeline.
// 256 threads / 8 warps, 1 CTA/SM, grid=148.
// R16: next window's x (fp32) cp.async'd into dead Q+KHI region (XF) during
// phase 3; converted from smem at iteration start. W sec0 issued at loop top
// (staged waits). PW prefetch moved right after af_all frees XA.
// smem: XA/PW 32K | B0/ATT 32K | Q 32K | KHI 32K | KLO 32K | VR/V 32K =192KB.
// XF (fp32 x staging, 64KB) = Q+KHI regions (dead during phase 3 / iter start).
// ---------------------------------------------------------------------------
#define FSM_XA   0
#define FSM_B0   32768
#define FSM_Q    65536
#define FSM_KHI  98304
#define FSM_KLO  131072
#define FSM_VR   163840
#define FSM_TOTAL 196608
#define FSM_XF   FSM_Q

__device__ __forceinline__ uint32_t prow_addr(int r, int u) {
    return (uint32_t)((r >> 1) * 128 + 16 * ((((r & 1) * 4) + u) ^ ((r >> 1) & 7)));
}

__global__ __launch_bounds__(256, 1)
void fused_all(const float* __restrict__ x, const __half* __restrict__ W16,
               const float* __restrict__ qkv_b, const __half* __restrict__ mask16,
               const __half* __restrict__ pw16, const float* __restrict__ bias_p,
               float* __restrict__ out) {
    extern __shared__ char smem[];
    const uint32_t sb = smem_u32(smem);
    const int tid = threadIdx.x, lane = tid & 31, w = tid >> 5;   // w: 0..7

    const int qrow = lane >> 2;        // 0..7
    const int qc   = (lane & 3) * 2;   // 0,2,4,6
    const int r8 = lane & 7, t4 = lane >> 3;

    // GEMM warp geometry (QKV + proj phases): 4m x 2n, warp tile 32x64
    const int wm = w & 3, wn = w >> 2;
    const int ga_row0 = wm * 32 + (t4 & 1) * 8 + r8;
    const int ga_us   = t4 >> 1;
    const int gb_roff = (t4 >> 1) * 8 + r8;
    const int gb_us   = t4 & 1;

    // attention warp geometry
    const int a_us = t4 >> 1, b_us = t4 & 1;
    const int a_row0 = w * 16 + (t4 & 1) * 8 + r8;   // warp owns 16 q-rows
    const int b_roff = (t4 >> 1) * 8 + r8;

    // ---- peel: prefetch FIRST window's x (fp32) into XF ----
    {
        const char* xb = (const char*)(x + (size_t)blockIdx.x * Nn * 128);
#pragma unroll
        for (int it = 0; it < 16; ++it) {
            int idx = it * 256 + tid;          // 0..4095 16B units
            cp_async16(sb + FSM_XF + idx * 16, xb + (size_t)idx * 16);
        }
        CP_COMMIT();
    }

    for (int b = blockIdx.x; b < Bb; b += NSM) {
        const int win = b & (NW - 1);
        const __half* mbase = mask16 + (size_t)win * Nn * Nn;

        // ---- issue W sec0 -> B0 (B0 dead after trailing sync) ----
#pragma unroll
        for (int it = 0; it < 8; ++it) {
            int idx = it * 256 + tid;
            int n = idx >> 4, g = idx & 15;
            cp_async16(sb + FSM_B0 + (g >> 3) * 16384 + n * 128 + 16 * ((g & 7) ^ (n & 7)),
                       W16 + (size_t)n * 128 + g * 8);
        }
        CP_COMMIT();

        // ---- wait x staged (W sec0 may still be in flight) ----
        CP_WAIT1();
        __syncthreads();

        // ---- convert XF (fp32, smem) -> XA (fp16 swizzled) ----
        {
            const float4* XF4 = reinterpret_cast<const float4*>(smem + FSM_XF);
#pragma unroll
            for (int it = 0; it < 8; ++it) {
                int idx = it * 256 + tid;
                int m = idx >> 4, g = idx & 15;
                float4 a = XF4[m * 32 + g * 2];
                float4 c = XF4[m * 32 + g * 2 + 1];
                uint4 u = {pack_h2(a.x, a.y), pack_h2(a.z, a.w),
                           pack_h2(c.x, c.y), pack_h2(c.z, c.w)};
                *reinterpret_cast<uint4*>(
                    (char*)smem + FSM_XA + (g >> 3) * 16384 + m * 128 +
                    16 * ((g & 7) ^ (m & 7))) = u;
            }
        }
        __syncthreads();

        // ---- A-fragments loaded ONCE, reused across all 3 sections ----
        uint32_t af_all[8][2][4];
#pragma unroll
        for (int s = 0; s < 8; ++s) {
            const int c = s >> 2;
            const int ku = (s & 3) * 2;
#pragma unroll
            for (int mf = 0; mf < 2; ++mf) {
                int row = ga_row0 + mf * 16;
                uint32_t addr = sb + FSM_XA + c * 16384 + row * 128 +
                                (((ku + ga_us) * 16) ^ ((row & 7) * 16));
                ldsm4(af_all[s][mf][0], af_all[s][mf][1], af_all[s][mf][2],
                      af_all[s][mf][3], addr);
            }
        }
        CP_WAIT0();        // W sec0 arrived (per-thread)
        __syncthreads();   // all XA reads done + W sec0 visible

        // ---- PW -> XA prefetch (XA dead after af_all) ----
#pragma unroll
        for (int it = 0; it < 8; ++it) {
            int idx = it * 256 + tid;
            int n = idx >> 4, g = idx & 15;
            cp_async16(sb + FSM_XA + (g >> 3) * 16384 + n * 128 + 16 * ((g & 7) ^ (n & 7)),
                       pw16 + (size_t)n * 128 + g * 8);
        }
        CP_COMMIT();

        // ================= Phase 1: QKV sections =================
#pragma unroll
        for (int sec = 0; sec < 3; ++sec) {
            if (sec < 2) {
                const uint32_t sBn = (sec == 0) ? (sb + FSM_VR) : (sb + FSM_B0);
                const __half* Bp = W16 + (size_t)((sec + 1) * 128) * 128;
#pragma unroll
                for (int it = 0; it < 8; ++it) {
                    int idx = it * 256 + tid;
                    int n = idx >> 4, g = idx & 15;
                    cp_async16(sBn + (g >> 3) * 16384 + n * 128 + 16 * ((g & 7) ^ (n & 7)),
                               Bp + (size_t)n * 128 + g * 8);
                }
                CP_COMMIT();
            }

            const uint32_t sB = (sec == 1) ? (sb + FSM_VR) : (sb + FSM_B0);
            float acc[2][8][4];
#pragma unroll
            for (int i = 0; i < 2; ++i)
#pragma unroll
                for (int j = 0; j < 8; ++j)
#pragma unroll
                    for (int k = 0; k < 4; ++k) acc[i][j][k] = 0.f;

            // mainloop: 8 k-steps of k=16 (A from registers)
#pragma unroll
            for (int s = 0; s < 8; ++s) {
                const int c = s >> 2;
                const int ku = (s & 3) * 2;
                uint32_t bf[8][2];
#pragma unroll
                for (int p = 0; p < 4; ++p) {
                    int row = wn * 64 + p * 16 + gb_roff;
                    uint32_t addr = sB + c * 16384 + row * 128 +
                                    (((ku + gb_us) * 16) ^ ((row & 7) * 16));
                    ldsm4(bf[p * 2][0], bf[p * 2][1], bf[p * 2 + 1][0],
                          bf[p * 2 + 1][1], addr);
                }
#pragma unroll
                for (int mf = 0; mf < 2; ++mf)
#pragma unroll
                    for (int nf = 0; nf < 8; ++nf)
                        mma_f16(acc[mf][nf], af_all[s][mf], bf[nf]);
            }

            // epilogue: + bias, pack fp16, store to head-chunked prow smem
#pragma unroll
            for (int mf = 0; mf < 2; ++mf) {
                const int r0 = wm * 32 + mf * 16 + qrow;
#pragma unroll
                for (int nf = 0; nf < 8; ++nf) {
                    const int col = wn * 64 + nf * 8 + qc;       // 0..127
                    float2 bv = *reinterpret_cast<const float2*>(&qkv_b[sec * 128 + col]);
                    float v00 = acc[mf][nf][0] + bv.x, v01 = acc[mf][nf][1] + bv.y;
                    float v10 = acc[mf][nf][2] + bv.x, v11 = acc[mf][nf][3] + bv.y;
                    const uint32_t hb = (uint32_t)(wn * 2 + (nf >> 2)) * 8192;
                    const uint32_t o0 = hb + prow_addr(r0, nf & 3) + qc * 2;
                    const uint32_t o1 = hb + prow_addr(r0 + 8, nf & 3) + qc * 2;
                    uint32_t p0, p1;
                    if (sec == 0) {
                        p0 = pack_h2(v00 * SCALE, v01 * SCALE);
                        p1 = pack_h2(v10 * SCALE, v11 * SCALE);
                        asm volatile("st.shared.b32 [%0], %1;" :: "r"(sb + FSM_Q + o0), "r"(p0) : "memory");
                        asm volatile("st.shared.b32 [%0], %1;" :: "r"(sb + FSM_Q + o1), "r"(p1) : "memory");
                    } else if (sec == 1) {
                        p0 = pack_h2(v00, v01);
                        p1 = pack_h2(v10, v11);
                        asm volatile("st.shared.b32 [%0], %1;" :: "r"(sb + FSM_KHI + o0), "r"(p0) : "memory");
                        asm volatile("st.shared.b32 [%0], %1;" :: "r"(sb + FSM_KHI + o1), "r"(p1) : "memory");
                        uint32_t l0 = pack_h2_lo(v00, v01);
                        uint32_t l1 = pack_h2_lo(v10, v11);
                        asm volatile("st.shared.b32 [%0], %1;" :: "r"(sb + FSM_KLO + o0), "r"(l0) : "memory");
                        asm volatile("st.shared.b32 [%0], %1;" :: "r"(sb + FSM_KLO + o1), "r"(l1) : "memory");
                    } else {
                        p0 = pack_h2(v00, v01);
                        p1 = pack_h2(v10, v11);
                        asm volatile("st.shared.b32 [%0], %1;" :: "r"(sb + FSM_VR + o0), "r"(p0) : "memory");
                        asm volatile("st.shared.b32 [%0], %1;" :: "r"(sb + FSM_VR + o1), "r"(p1) : "memory");
                    }
                }
            }

            if (sec < 2) CP_WAIT0();
            __syncthreads();
        }

        // ---- mask -> registers (head-invariant; packed fp16; L2-hot) ----
        uint32_t mreg[16][2];
        {
            const __half* mr = mbase + (w * 16 + qrow) * Nn + qc;
#pragma unroll
            for (int nf = 0; nf < 16; ++nf) {
                mreg[nf][0] = *reinterpret_cast<const uint32_t*>(mr + nf * 8);
                mreg[nf][1] = *reinterpret_cast<const uint32_t*>(mr + 8 * Nn + nf * 8);
            }
        }

        // ================= Phase 2: attention (no syncs in head loop) ======
        // all heads' Q fragments prefetched (8 ldsm4, 32 regs)
        uint32_t qf_all[Hh][2][4];
#pragma unroll
        for (int h = 0; h < Hh; ++h)
#pragma unroll
            for (int s = 0; s < 2; ++s)
                ldsm4(qf_all[h][s][0], qf_all[h][s][1], qf_all[h][s][2],
                      qf_all[h][s][3],
                      sb + FSM_Q + h * 8192 + prow_addr(a_row0, s * 2 + a_us));

#pragma unroll
        for (int h = 0; h < Hh; ++h) {
            const uint32_t khb = sb + FSM_KHI + h * 8192;
            const uint32_t klb = sb + FSM_KLO + h * 8192;
            const uint32_t vb  = sb + FSM_VR  + h * 8192;

            // acc init from register mask cache
            float acc[16][4];
#pragma unroll
            for (int nf = 0; nf < 16; ++nf) {
                float2 f0 = __half22float2(*reinterpret_cast<const __half2*>(&mreg[nf][0]));
                float2 f1 = __half22float2(*reinterpret_cast<const __half2*>(&mreg[nf][1]));
                acc[nf][0] = f0.x; acc[nf][1] = f0.y;
                acc[nf][2] = f1.x; acc[nf][3] = f1.y;
            }

            // S mma: 2 k-steps; hi pass then lo pass per k-step
#pragma unroll
            for (int s = 0; s < 2; ++s) {
                const int ku = s * 2;
#pragma unroll
                for (int p = 0; p < 8; ++p) {
                    uint32_t off = prow_addr(p * 16 + b_roff, ku + b_us);
                    uint32_t kh[2][2];
                    ldsm4(kh[0][0], kh[0][1], kh[1][0], kh[1][1], khb + off);
                    mma_f16(acc[p * 2 + 0], qf_all[h][s], kh[0]);
                    mma_f16(acc[p * 2 + 1], qf_all[h][s], kh[1]);
                }
#pragma unroll
                for (int p = 0; p < 8; ++p) {
                    uint32_t off = prow_addr(p * 16 + b_roff, ku + b_us);
                    uint32_t kl[2][2];
                    ldsm4(kl[0][0], kl[0][1], kl[1][0], kl[1][1], klb + off);
                    mma_f16(acc[p * 2 + 0], qf_all[h][s], kl[0]);
                    mma_f16(acc[p * 2 + 1], qf_all[h][s], kl[1]);
                }
            }

            // register softmax — TREE reductions
            float inv[2];
#pragma unroll
            for (int hf = 0; hf < 2; ++hf) {
                float t[16];
#pragma unroll
                for (int nf = 0; nf < 16; ++nf)
                    t[nf] = fmaxf(acc[nf][hf * 2], acc[nf][hf * 2 + 1]);
#pragma unroll
                for (int st = 8; st > 0; st >>= 1)
#pragma unroll
                    for (int i = 0; i < 16; ++i)
                        if (i < st) t[i] = fmaxf(t[i], t[i + st]);
                float mx = fmaxf(t[0], __shfl_xor_sync(0xffffffffu, t[0], 1));
                mx = fmaxf(mx, __shfl_xor_sync(0xffffffffu, mx, 2));

#pragma unroll
                for (int nf = 0; nf < 16; ++nf) {
                    float e0 = __expf(acc[nf][hf * 2] - mx);
                    float e1 = __expf(acc[nf][hf * 2 + 1] - mx);
                    acc[nf][hf * 2] = e0;
                    acc[nf][hf * 2 + 1] = e1;
                    t[nf] = e0 + e1;
                }
#pragma unroll
                for (int st = 8; st > 0; st >>= 1)
#pragma unroll
                    for (int i = 0; i < 16; ++i)
                        if (i < st) t[i] += t[i + st];
                float sum = t[0] + __shfl_xor_sync(0xffffffffu, t[0], 1);
                sum += __shfl_xor_sync(0xffffffffu, sum, 2);
                inv[hf] = 1.f / sum;
            }

            // PV mma: P straight from registers (FA2 repack)
            float o[4][4];
#pragma unroll
            for (int j = 0; j < 4; ++j)
#pragma unroll
                for (int k = 0; k < 4; ++k) o[j][k] = 0.f;

#pragma unroll
            for (int s2 = 0; s2 < 8; ++s2) {
                uint32_t pf[4] = {
                    pack_h2(acc[2 * s2][0],     acc[2 * s2][1]),
                    pack_h2(acc[2 * s2][2],     acc[2 * s2][3]),
                    pack_h2(acc[2 * s2 + 1][0], acc[2 * s2 + 1][1]),
                    pack_h2(acc[2 * s2 + 1][2], acc[2 * s2 + 1][3])};
                uint32_t vf[4][2];
                const int jrow = s2 * 16 + (t4 & 1) * 8 + r8;
#pragma unroll
                for (int nu = 0; nu < 2; ++nu) {
                    ldsm4t(vf[nu * 2][0], vf[nu * 2][1], vf[nu * 2 + 1][0],
                           vf[nu * 2 + 1][1], vb + prow_addr(jrow, nu * 2 + (t4 >> 1)));
                }
#pragma unroll
                for (int nf = 0; nf < 4; ++nf)
                    mma_f16(o[nf], pf, vf[nf]);
            }

            // O -> ATT tile (overlay B0), GEMM-A swizzled layout, fp16
            {
                const int r0 = w * 16 + qrow;
#pragma unroll
                for (int nf = 0; nf < 4; ++nf) {
                    int g = h * 4 + nf;              // 16B col unit 0..15
                    uint32_t baseu = sb + FSM_B0 + (g >> 3) * 16384;
                    uint32_t a0 = baseu + r0 * 128 + 16 * ((g & 7) ^ (r0 & 7)) + qc * 2;
                    int r1 = r0 + 8;
                    uint32_t a1 = baseu + r1 * 128 + 16 * ((g & 7) ^ (r1 & 7)) + qc * 2;
                    uint32_t p0 = pack_h2(o[nf][0] * inv[0], o[nf][1] * inv[0]);
                    uint32_t p1 = pack_h2(o[nf][2] * inv[1], o[nf][3] * inv[1]);
                    asm volatile("st.shared.b32 [%0], %1;" :: "r"(a0), "r"(p0) : "memory");
                    asm volatile("st.shared.b32 [%0], %1;" :: "r"(a1), "r"(p1) : "memory");
                }
            }
        }

        __syncthreads();   // ATT complete; Q/KHI/KLO/VR reads done

        // ---- prefetch NEXT window's x (fp32) into XF (overlaps phase 3) ----
        if (b + NSM < Bb) {
            const char* xb = (const char*)(x + (size_t)(b + NSM) * Nn * 128);
#pragma unroll
            for (int it = 0; it < 16; ++it) {
                int idx = it * 256 + tid;
                cp_async16(sb + FSM_XF + idx * 16, xb + (size_t)idx * 16);
            }
            CP_COMMIT();
        }

        // ================= Phase 3: proj GEMM from smem =================
        // (PW already arrived — waited at end of sec0)
        {
            float acc[2][8][4];
#pragma unroll
            for (int i = 0; i < 2; ++i)
#pragma unroll
                for (int j = 0; j < 8; ++j)
#pragma unroll
                    for (int k = 0; k < 4; ++k) acc[i][j][k] = 0.f;

#pragma unroll
            for (int s = 0; s < 8; ++s) {
                const int c = s >> 2;
                const int ku = (s & 3) * 2;
                uint32_t af[2][4], bf[8][2];
#pragma unroll
                for (int mf = 0; mf < 2; ++mf) {
                    int row = ga_row0 + mf * 16;
                    uint32_t addr = sb + FSM_B0 + c * 16384 + row * 128 +
                                    (((ku + ga_us) * 16) ^ ((row & 7) * 16));
                    ldsm4(af[mf][0], af[mf][1], af[mf][2], af[mf][3], addr);
                }
#pragma unroll
                for (int p = 0; p < 4; ++p) {
                    int row = wn * 64 + p * 16 + gb_roff;
                    uint32_t addr = sb + FSM_XA + c * 16384 + row * 128 +
                                    (((ku + gb_us) * 16) ^ ((row & 7) * 16));
                    ldsm4(bf[p * 2][0], bf[p * 2][1], bf[p * 2 + 1][0],
                          bf[p * 2 + 1][1], addr);
                }
#pragma unroll
                for (int mf = 0; mf < 2; ++mf)
#pragma unroll
                    for (int nf = 0; nf < 8; ++nf)
                        mma_f16(acc[mf][nf], af[mf], bf[nf]);
            }

#pragma unroll
            for (int mf = 0; mf < 2; ++mf) {
                const int rowg = b * 128 + wm * 32 + mf * 16 + qrow;
#pragma unroll
                for (int nf = 0; nf < 8; ++nf) {
                    const int col = wn * 64 + nf * 8 + qc;
                    float2 bv = *reinterpret_cast<const float2*>(&bias_p[col]);
                    float2 o0 = {acc[mf][nf][0] + bv.x, acc[mf][nf][1] + bv.y};
                    float2 o1 = {acc[mf][nf][2] + bv.x, acc[mf][nf][3] + bv.y};
                    *reinterpret_cast<float2*>(out + (size_t)rowg * 128 + col) = o0;
                    *reinterpret_cast<float2*>(out + (size_t)(rowg + 8) * 128 + col) = o1;
                }
            }
        }

        // all reads of B0/XA done before next loop-top cp.async overwrites
        __syncthreads();
    }
}

// ---------------------------------------------------------------------------
// Launch
// ---------------------------------------------------------------------------
extern "C" void kernel_launch(void* const* d_in, const int* in_sizes, int n_in,
                              void* d_out, int out_size) {
    const float* x      = (const float*)d_in[0];
    const float* mask   = (const float*)d_in[1];
    const float* qkv_w  = (const float*)d_in[2];
    const float* qkv_b  = (const float*)d_in[3];
    const float* proj_w = (const float*)d_in[4];
    const float* proj_b = (const float*)d_in[5];
    float* out = (float*)d_out;

    __half *p_w16, *p_pw16, *p_mask16;
    cudaGetSymbolAddress((void**)&p_w16, g_w16);
    cudaGetSymbolAddress((void**)&p_pw16, g_pw16);
    cudaGetSymbolAddress((void**)&p_mask16, g_mask16);

    cudaFuncSetAttribute(fused_all, cudaFuncAttributeMaxDynamicSharedMemorySize,
                         FSM_TOTAL);

    // 0) fp16 prepass (weights + mask)
    prep16<<<(PREP_TOT + 255) / 256, 256>>>(mask, qkv_w, proj_w);

    // 1) fully fused persistent kernel: 148 CTAs loop over 2048 windows
    fused_all<<<NSM, 256, FSM_TOTAL>>>(x, p_w16, qkv_b, p_mask16, p_pw16,
                                       proj_b, out);
}